// round 3
// baseline (speedup 1.0000x reference)
#include <cuda_runtime.h>
#include <cstdint>

// ---------------------------------------------------------------------------
// Problem constants
// ---------------------------------------------------------------------------
#define BATCH  256
#define SEQ    2048
#define IND    4
#define HID    256
#define FOURH  1024

// LSTM recurrence partitioning:
//   16 clusters x 8 CTAs = 128 CTAs.
//   Each cluster owns MG=16 batch rows.
//   Each CTA (rank r) owns 32 h-indices J_r=[32r,32r+32) -> 128 W_hh rows
//   (4 gates x 32), kept resident in SMEM as tf32.
#define CLUSTER 8
#define NCLUST  16
#define MG      16      // batch rows per cluster
#define NCTA    128     // W rows per CTA (gate*32 + jj)
#define JPC     32      // h indices per CTA
#define THREADS 128     // 4 warps

// SMEM layout strides (floats). 260 = 4 (mod 32) -> conflict-free mma frags.
#define WS_STRIDE 260
#define AS_STRIDE 260
#define ZS_STRIDE 132

#define SMEM_FLOATS (NCTA*WS_STRIDE + MG*AS_STRIDE + MG*ZS_STRIDE + MG*JPC + NCTA*IND + NCTA + MG*IND)
#define SMEM_BYTES  (SMEM_FLOATS * 4)

// ---------------------------------------------------------------------------
// Global scratch (no cudaMalloc allowed)
// ---------------------------------------------------------------------------
__device__ float g_h[2][BATCH * HID];      // double-buffered hidden state
__device__ float g_feat[2 * BATCH];        // [0..255]=conv_feat, [256..511]=ksim

// ---------------------------------------------------------------------------
// helpers
// ---------------------------------------------------------------------------
__device__ __forceinline__ float rtf32(float v) {
    uint32_t r;
    asm("cvt.rna.tf32.f32 %0, %1;" : "=r"(r) : "f"(v));
    return __uint_as_float(r);
}
__device__ __forceinline__ float fast_sigmoid(float x) {
    float e = __expf(-x);               // e in [0, inf]; inf -> result 0 (correct)
    return __fdividef(1.0f, 1.0f + e);
}
__device__ __forceinline__ float fast_tanh(float x) {
    x = fminf(fmaxf(x, -20.0f), 20.0f); // tanh saturates exactly at |x|>=20 in fp32
    float e = __expf(-2.0f * x);
    return __fdividef(1.0f - e, 1.0f + e);
}

// ---------------------------------------------------------------------------
// Kernel 1: conv_feat + kernel_sim (per batch row reductions over SEQ x 4)
// ---------------------------------------------------------------------------
__global__ void feat_kernel(const float* __restrict__ x,
                            const float* __restrict__ conv_w,
                            const float* __restrict__ conv_b) {
    __shared__ float r0[256];
    __shared__ float r1[256];
    int b = blockIdx.x, tid = threadIdx.x;
    float4 cw = *(const float4*)conv_w;
    float cb = conv_b[0];
    const float4* xr = (const float4*)(x + (size_t)b * SEQ * IND);
    float ssig = 0.f, ssq = 0.f;
    for (int s = tid; s < SEQ; s += 256) {
        float4 v = xr[s];
        float d = v.x * cw.x + v.y * cw.y + v.z * cw.z + v.w * cw.w + cb;
        ssig += fast_sigmoid(d);
        ssq  += v.x * v.x + v.y * v.y + v.z * v.z + v.w * v.w;
    }
    r0[tid] = ssig; r1[tid] = ssq;
    __syncthreads();
    for (int o = 128; o > 0; o >>= 1) {
        if (tid < o) { r0[tid] += r0[tid + o]; r1[tid] += r1[tid + o]; }
        __syncthreads();
    }
    if (tid == 0) {
        g_feat[b]         = r0[0] * (1.0f / SEQ);
        g_feat[BATCH + b] = __expf(-r1[0]);   // GAMMA = 1; underflows to 0 (matches jax)
    }
}

// ---------------------------------------------------------------------------
// Kernel 2: LSTM recurrence. One cluster of 8 CTAs per 16 batch rows.
// mma.sync.m16n8k8 tf32; W_hh slice resident in SMEM; h exchanged through L2
// with barrier.cluster (release/acquire) per step; c-state resident in SMEM.
// ---------------------------------------------------------------------------
__global__ void __cluster_dims__(CLUSTER, 1, 1) __launch_bounds__(THREADS, 1)
lstm_kernel(const float* __restrict__ x,
            const float* __restrict__ W_ih,
            const float* __restrict__ W_hh,
            const float* __restrict__ b_ih,
            const float* __restrict__ b_hh) {
    extern __shared__ float sm[];
    float* Ws    = sm;                         // [128][260] tf32 W_hh slice
    float* As    = Ws    + NCTA * WS_STRIDE;   // [16][260]  h tile (A operand)
    float* Zs    = As    + MG   * AS_STRIDE;   // [16][132]  z tile
    float* Cs    = Zs    + MG   * ZS_STRIDE;   // [16][32]   c state
    float* WihS  = Cs    + MG   * JPC;         // [128][4]
    float* BiasS = WihS  + NCTA * IND;         // [128]
    float* Xs    = BiasS + NCTA;               // [16][4]

    const int tid   = threadIdx.x;
    const int cid   = blockIdx.x / CLUSTER;
    const int rank  = blockIdx.x % CLUSTER;
    const int bbase = cid * MG;
    const int j0    = rank * JPC;

    // ---- init: load resident weight slice (pre-rounded to tf32) ----
    for (int i = tid; i < NCTA * HID; i += THREADS) {
        int n = i / HID, k = i - n * HID;       // n local: gate*32 + jj
        int gate = n >> 5, jj = n & 31;
        int grow = gate * HID + j0 + jj;
        uint32_t tv;
        asm("cvt.rna.tf32.f32 %0, %1;" : "=r"(tv) : "f"(W_hh[grow * HID + k]));
        ((uint32_t*)Ws)[n * WS_STRIDE + k] = tv;
    }
    for (int i = tid; i < NCTA; i += THREADS) {
        int gate = i >> 5, jj = i & 31;
        int grow = gate * HID + j0 + jj;
        BiasS[i] = b_ih[grow] + b_hh[grow];
        WihS[i * 4 + 0] = W_ih[grow * IND + 0];
        WihS[i * 4 + 1] = W_ih[grow * IND + 1];
        WihS[i * 4 + 2] = W_ih[grow * IND + 2];
        WihS[i * 4 + 3] = W_ih[grow * IND + 3];
    }
    for (int i = tid; i < MG * JPC; i += THREADS) {
        Cs[i] = 0.0f;
        int bb = i / JPC, jj = i - bb * JPC;
        g_h[0][(bbase + bb) * HID + j0 + jj] = 0.0f;   // h_0 = 0
    }
    asm volatile("barrier.cluster.arrive.aligned;" ::: "memory");
    asm volatile("barrier.cluster.wait.aligned;"   ::: "memory");

    const int warp = tid >> 5, lane = tid & 31;
    const int gID = lane >> 2, tig = lane & 3;
    const uint32_t* Au = (const uint32_t*)As;
    const uint32_t* Bu = (const uint32_t*)Ws;

    for (int t = 0; t < SEQ; ++t) {
        const int p = t & 1;
        const float* hin = g_h[p];

        // stage h tile (16 x 256) into SMEM, and x_t (16 x 4)
        for (int i = tid; i < MG * (HID / 4); i += THREADS) {
            int row = i >> 6, c4 = i & 63;
            float4 v = *(const float4*)(hin + (bbase + row) * HID + c4 * 4);
            *(float4*)(As + row * AS_STRIDE + c4 * 4) = v;
        }
        if (tid < MG) {
            float4 xv = *(const float4*)(x + ((size_t)(bbase + tid) * SEQ + t) * IND);
            *(float4*)(Xs + tid * 4) = xv;
        }
        __syncthreads();

        // ---- z_wh = h @ W^T : warp computes n in [warp*32, warp*32+32) ----
        float acc[4][4];
        #pragma unroll
        for (int s = 0; s < 4; ++s)
            #pragma unroll
            for (int q = 0; q < 4; ++q) acc[s][q] = 0.0f;

        #pragma unroll 4
        for (int k0 = 0; k0 < HID; k0 += 8) {
            uint32_t a0 = Au[(gID)     * AS_STRIDE + k0 + tig];
            uint32_t a1 = Au[(gID + 8) * AS_STRIDE + k0 + tig];
            uint32_t a2 = Au[(gID)     * AS_STRIDE + k0 + tig + 4];
            uint32_t a3 = Au[(gID + 8) * AS_STRIDE + k0 + tig + 4];
            #pragma unroll
            for (int s = 0; s < 4; ++s) {
                int n = warp * 32 + s * 8 + gID;
                uint32_t b0 = Bu[n * WS_STRIDE + k0 + tig];
                uint32_t b1 = Bu[n * WS_STRIDE + k0 + tig + 4];
                asm("mma.sync.aligned.m16n8k8.row.col.f32.tf32.tf32.f32 "
                    "{%0,%1,%2,%3},{%4,%5,%6,%7},{%8,%9},{%0,%1,%2,%3};"
                    : "+f"(acc[s][0]), "+f"(acc[s][1]), "+f"(acc[s][2]), "+f"(acc[s][3])
                    : "r"(a0), "r"(a1), "r"(a2), "r"(a3), "r"(b0), "r"(b1));
            }
        }
        #pragma unroll
        for (int s = 0; s < 4; ++s) {
            int n = warp * 32 + s * 8;
            Zs[(gID)     * ZS_STRIDE + n + 2 * tig]     = acc[s][0];
            Zs[(gID)     * ZS_STRIDE + n + 2 * tig + 1] = acc[s][1];
            Zs[(gID + 8) * ZS_STRIDE + n + 2 * tig]     = acc[s][2];
            Zs[(gID + 8) * ZS_STRIDE + n + 2 * tig + 1] = acc[s][3];
        }
        __syncthreads();

        // ---- gates: thread owns (b = tid>>3, jj = 4*(tid&7) .. +3) ----
        {
            int b   = tid >> 3;
            int jjb = (tid & 7) << 2;
            float4 xv = *(float4*)(Xs + b * 4);
            float4 c4 = *(float4*)(Cs + b * JPC + jjb);
            float4 z0 = *(float4*)(Zs + b * ZS_STRIDE +      jjb);   // i
            float4 z1 = *(float4*)(Zs + b * ZS_STRIDE + 32 + jjb);   // f
            float4 z2 = *(float4*)(Zs + b * ZS_STRIDE + 64 + jjb);   // g
            float4 z3 = *(float4*)(Zs + b * ZS_STRIDE + 96 + jjb);   // o
            float zi[4] = {z0.x, z0.y, z0.z, z0.w};
            float zf[4] = {z1.x, z1.y, z1.z, z1.w};
            float zg[4] = {z2.x, z2.y, z2.z, z2.w};
            float zo[4] = {z3.x, z3.y, z3.z, z3.w};
            float co[4] = {c4.x, c4.y, c4.z, c4.w};
            float cN[4], hN[4];
            #pragma unroll
            for (int u = 0; u < 4; ++u) {
                int n0 = jjb + u;
                float4 wi = *(float4*)(WihS + (n0)      * 4);
                float4 wf = *(float4*)(WihS + (32 + n0) * 4);
                float4 wg = *(float4*)(WihS + (64 + n0) * 4);
                float4 wo = *(float4*)(WihS + (96 + n0) * 4);
                float ai = zi[u] + BiasS[n0]      + xv.x*wi.x + xv.y*wi.y + xv.z*wi.z + xv.w*wi.w;
                float af = zf[u] + BiasS[32 + n0] + xv.x*wf.x + xv.y*wf.y + xv.z*wf.z + xv.w*wf.w;
                float ag = zg[u] + BiasS[64 + n0] + xv.x*wg.x + xv.y*wg.y + xv.z*wg.z + xv.w*wg.w;
                float ao = zo[u] + BiasS[96 + n0] + xv.x*wo.x + xv.y*wo.y + xv.z*wo.z + xv.w*wo.w;
                float gi = fast_sigmoid(ai);
                float gf = fast_sigmoid(af);
                float gg = fast_tanh(ag);
                float go = fast_sigmoid(ao);
                float cn = gf * co[u] + gi * gg;
                cN[u] = cn;
                hN[u] = rtf32(go * fast_tanh(cn));   // pre-round for next mma
            }
            *(float4*)(Cs + b * JPC + jjb) = make_float4(cN[0], cN[1], cN[2], cN[3]);
            *(float4*)(&g_h[p ^ 1][(bbase + b) * HID + j0 + jjb]) =
                make_float4(hN[0], hN[1], hN[2], hN[3]);
        }
        // release own h writes, acquire everyone else's (cluster scope)
        asm volatile("barrier.cluster.arrive.aligned;" ::: "memory");
        asm volatile("barrier.cluster.wait.aligned;"   ::: "memory");
    }
    // final h lives in g_h[0] (2048 steps: last write targets buffer 0)
}

// ---------------------------------------------------------------------------
// Kernel 3: head  combined=[conv_feat, h, ksim] -> fc+relu -> out -> softmax
// ---------------------------------------------------------------------------
__global__ void head_kernel(const float* __restrict__ fc_w,
                            const float* __restrict__ fc_b,
                            const float* __restrict__ out_w,
                            const float* __restrict__ out_b,
                            float* __restrict__ out) {
    __shared__ float hsh[HID];
    __shared__ float r0[256];
    __shared__ float r1[256];
    int b = blockIdx.x, tid = threadIdx.x;
    hsh[tid] = g_h[0][b * HID + tid];
    __syncthreads();
    float cf = g_feat[b], ks = g_feat[BATCH + b];
    const float* wr = fc_w + (size_t)tid * (HID + 2);
    float acc = fc_b[tid] + wr[0] * cf + wr[HID + 1] * ks;
    #pragma unroll 8
    for (int k = 0; k < HID; ++k) acc += wr[1 + k] * hsh[k];
    float hid = fmaxf(acc, 0.0f);
    r0[tid] = hid * out_w[tid];
    r1[tid] = hid * out_w[HID + tid];
    __syncthreads();
    for (int o = 128; o > 0; o >>= 1) {
        if (tid < o) { r0[tid] += r0[tid + o]; r1[tid] += r1[tid + o]; }
        __syncthreads();
    }
    if (tid == 0) {
        float l0 = r0[0] + out_b[0];
        float l1 = r1[0] + out_b[1];
        float m  = fmaxf(l0, l1);
        float e0 = __expf(l0 - m), e1 = __expf(l1 - m);
        float inv = __fdividef(1.0f, e0 + e1);
        out[b * 2 + 0] = e0 * inv;
        out[b * 2 + 1] = e1 * inv;
    }
}

// ---------------------------------------------------------------------------
// launch
// ---------------------------------------------------------------------------
extern "C" void kernel_launch(void* const* d_in, const int* in_sizes, int n_in,
                              void* d_out, int out_size) {
    const float* x      = (const float*)d_in[0];
    const float* conv_w = (const float*)d_in[1];
    const float* conv_b = (const float*)d_in[2];
    const float* W_ih   = (const float*)d_in[3];
    const float* W_hh   = (const float*)d_in[4];
    const float* b_ih   = (const float*)d_in[5];
    const float* b_hh   = (const float*)d_in[6];
    const float* fc_w   = (const float*)d_in[7];
    const float* fc_b   = (const float*)d_in[8];
    const float* out_w  = (const float*)d_in[9];
    const float* out_b  = (const float*)d_in[10];
    float* out = (float*)d_out;

    cudaFuncSetAttribute(lstm_kernel, cudaFuncAttributeMaxDynamicSharedMemorySize,
                         SMEM_BYTES);

    feat_kernel<<<BATCH, 256>>>(x, conv_w, conv_b);
    lstm_kernel<<<NCLUST * CLUSTER, THREADS, SMEM_BYTES>>>(x, W_ih, W_hh, b_ih, b_hh);
    head_kernel<<<BATCH, 256>>>(fc_w, fc_b, out_w, out_b, out);
}

// round 4
// speedup vs baseline: 1.0034x; 1.0034x over previous
#include <cuda_runtime.h>
#include <cstdint>

// ---------------------------------------------------------------------------
// Problem constants
// ---------------------------------------------------------------------------
#define BATCH  256
#define SEQ    2048
#define IND    4
#define HID    256
#define FOURH  1024

// Partitioning: 16 clusters x 8 CTAs = 128 CTAs (one per SM, co-resident).
// Cluster owns MG=16 batch rows; CTA rank r owns h-indices [32r, 32r+32)
// -> 128 W_hh rows (4 gates x 32) x 256 cols, held as tf32 REGISTER fragments.
#define CLUSTER 8
#define NCLUST  16
#define MG      16
#define NCTA    128     // W rows per CTA
#define JPC     32      // h indices per CTA
#define THREADS 256     // 8 warps; warp w owns local n-rows [16w, 16w+16)

#define ZS_STRIDE 132

// ---------------------------------------------------------------------------
// Global scratch (no cudaMalloc allowed)
// ---------------------------------------------------------------------------
__device__ float g_h[2][BATCH * HID];      // double-buffered hidden state
__device__ float g_feat[2 * BATCH];        // [0..255]=conv_feat, [256..511]=ksim

// ---------------------------------------------------------------------------
// helpers
// ---------------------------------------------------------------------------
__device__ __forceinline__ uint32_t tf32u(float v) {
    uint32_t r;
    asm("cvt.rna.tf32.f32 %0, %1;" : "=r"(r) : "f"(v));
    return r;
}
__device__ __forceinline__ float rtf32(float v) {
    return __uint_as_float(tf32u(v));
}
__device__ __forceinline__ float fast_sigmoid(float x) {
    float e = __expf(-x);
    return __fdividef(1.0f, 1.0f + e);
}
__device__ __forceinline__ float fast_tanh(float x) {
    x = fminf(fmaxf(x, -20.0f), 20.0f);
    float e = __expf(-2.0f * x);
    return __fdividef(1.0f - e, 1.0f + e);
}

// ---------------------------------------------------------------------------
// Kernel 1: conv_feat + kernel_sim
// ---------------------------------------------------------------------------
__global__ void feat_kernel(const float* __restrict__ x,
                            const float* __restrict__ conv_w,
                            const float* __restrict__ conv_b) {
    __shared__ float r0[256];
    __shared__ float r1[256];
    int b = blockIdx.x, tid = threadIdx.x;
    float4 cw = *(const float4*)conv_w;
    float cb = conv_b[0];
    const float4* xr = (const float4*)(x + (size_t)b * SEQ * IND);
    float ssig = 0.f, ssq = 0.f;
    for (int s = tid; s < SEQ; s += 256) {
        float4 v = xr[s];
        float d = v.x * cw.x + v.y * cw.y + v.z * cw.z + v.w * cw.w + cb;
        ssig += fast_sigmoid(d);
        ssq  += v.x * v.x + v.y * v.y + v.z * v.z + v.w * v.w;
    }
    r0[tid] = ssig; r1[tid] = ssq;
    __syncthreads();
    for (int o = 128; o > 0; o >>= 1) {
        if (tid < o) { r0[tid] += r0[tid + o]; r1[tid] += r1[tid + o]; }
        __syncthreads();
    }
    if (tid == 0) {
        g_feat[b]         = r0[0] * (1.0f / SEQ);
        g_feat[BATCH + b] = __expf(-r1[0]);
    }
}

// ---------------------------------------------------------------------------
// Kernel 2: LSTM recurrence.
//   - W_hh slice in per-lane tf32 register fragments (loaded once)
//   - h staged into fragment-interleaved SMEM: As[k][il(row)], il conflict-free
//   - mma.sync.m16n8k8.tf32, 8 warps (warp w -> local n in [16w,16w+16))
//   - h exchanged via global (L2) with one cluster barrier per step
// ---------------------------------------------------------------------------
__global__ void __cluster_dims__(CLUSTER, 1, 1) __launch_bounds__(THREADS, 1)
lstm_kernel(const float* __restrict__ x,
            const float* __restrict__ W_ih,
            const float* __restrict__ W_hh,
            const float* __restrict__ b_ih,
            const float* __restrict__ b_hh) {
    __shared__ float As[HID * 16];          // [k][il(row)]  16 KB
    __shared__ float Zs[MG * ZS_STRIDE];    // [b][n]        8.4 KB
    __shared__ float Cs[MG * JPC];          // c state
    __shared__ float WihS[NCTA * IND];
    __shared__ float BiasS[NCTA];
    __shared__ float Xs[MG * IND];

    const int tid   = threadIdx.x;
    const int cid   = blockIdx.x / CLUSTER;
    const int rank  = blockIdx.x % CLUSTER;
    const int bbase = cid * MG;
    const int j0    = rank * JPC;
    const int warp  = tid >> 5, lane = tid & 31;
    const int g     = lane >> 2, tig = lane & 3;

    // ---- one-time: W_hh register fragments (tf32), W_ih/bias to SMEM ----
    uint32_t Breg[2][32][2];
    #pragma unroll
    for (int s = 0; s < 2; ++s) {
        int nl   = warp * 16 + s * 8 + g;        // local n-row
        int gate = nl >> 5, jj = nl & 31;
        const float* wrow = W_hh + (size_t)(gate * HID + j0 + jj) * HID;
        #pragma unroll
        for (int kt = 0; kt < 32; ++kt) {
            Breg[s][kt][0] = tf32u(wrow[kt * 8 + tig]);
            Breg[s][kt][1] = tf32u(wrow[kt * 8 + tig + 4]);
        }
    }
    if (tid < NCTA) {
        int gate = tid >> 5, jj = tid & 31;
        int grow = gate * HID + j0 + jj;
        BiasS[tid] = b_ih[grow] + b_hh[grow];
        WihS[tid * 4 + 0] = W_ih[grow * IND + 0];
        WihS[tid * 4 + 1] = W_ih[grow * IND + 1];
        WihS[tid * 4 + 2] = W_ih[grow * IND + 2];
        WihS[tid * 4 + 3] = W_ih[grow * IND + 3];
    }
    #pragma unroll
    for (int i = tid; i < MG * JPC; i += THREADS) {
        Cs[i] = 0.0f;
        int bb = i / JPC, jj = i - bb * JPC;
        g_h[0][(bbase + bb) * HID + j0 + jj] = 0.0f;   // h_0 = 0
    }
    asm volatile("barrier.cluster.arrive.aligned;" ::: "memory");
    asm volatile("barrier.cluster.wait.aligned;"   ::: "memory");

    for (int t = 0; t < SEQ; ++t) {
        const int p = t & 1;
        const float* hin = g_h[p];

        // ---- stage h tile (16 x 256) -> interleaved As[k][il(row)] ----
        #pragma unroll
        for (int it = 0; it < 4; ++it) {
            int i   = it * THREADS + tid;
            int row = i & 15;
            int c4  = i >> 4;                    // 0..63
            float4 v = *(const float4*)(hin + (size_t)(bbase + row) * HID + c4 * 4);
            int pr = (row < 8) ? (row * 2) : ((row - 8) * 2 + 1);
            As[(c4 * 4 + 0) * 16 + pr] = v.x;
            As[(c4 * 4 + 1) * 16 + pr] = v.y;
            As[(c4 * 4 + 2) * 16 + pr] = v.z;
            As[(c4 * 4 + 3) * 16 + pr] = v.w;
        }
        if (tid < MG) {
            float4 xv = *(const float4*)(x + ((size_t)(bbase + tid) * SEQ + t) * IND);
            *(float4*)(Xs + tid * 4) = xv;
        }
        __syncthreads();

        // ---- z = h @ W^T for this warp's 16 n-rows (B in registers) ----
        float acc0[4] = {0.f, 0.f, 0.f, 0.f};
        float acc1[4] = {0.f, 0.f, 0.f, 0.f};
        const uint32_t* Au = (const uint32_t*)As;
        #pragma unroll
        for (int kt = 0; kt < 32; ++kt) {
            uint2 A01 = *(const uint2*)(Au + (kt * 8 + tig) * 16 + 2 * g);
            uint2 A23 = *(const uint2*)(Au + (kt * 8 + tig + 4) * 16 + 2 * g);
            asm("mma.sync.aligned.m16n8k8.row.col.f32.tf32.tf32.f32 "
                "{%0,%1,%2,%3},{%4,%5,%6,%7},{%8,%9},{%0,%1,%2,%3};"
                : "+f"(acc0[0]), "+f"(acc0[1]), "+f"(acc0[2]), "+f"(acc0[3])
                : "r"(A01.x), "r"(A01.y), "r"(A23.x), "r"(A23.y),
                  "r"(Breg[0][kt][0]), "r"(Breg[0][kt][1]));
            asm("mma.sync.aligned.m16n8k8.row.col.f32.tf32.tf32.f32 "
                "{%0,%1,%2,%3},{%4,%5,%6,%7},{%8,%9},{%0,%1,%2,%3};"
                : "+f"(acc1[0]), "+f"(acc1[1]), "+f"(acc1[2]), "+f"(acc1[3])
                : "r"(A01.x), "r"(A01.y), "r"(A23.x), "r"(A23.y),
                  "r"(Breg[1][kt][0]), "r"(Breg[1][kt][1]));
        }
        {
            int n0 = warp * 16;
            *(float2*)(Zs + (g)     * ZS_STRIDE + n0 +     2 * tig) = make_float2(acc0[0], acc0[1]);
            *(float2*)(Zs + (g + 8) * ZS_STRIDE + n0 +     2 * tig) = make_float2(acc0[2], acc0[3]);
            *(float2*)(Zs + (g)     * ZS_STRIDE + n0 + 8 + 2 * tig) = make_float2(acc1[0], acc1[1]);
            *(float2*)(Zs + (g + 8) * ZS_STRIDE + n0 + 8 + 2 * tig) = make_float2(acc1[2], acc1[3]);
        }
        __syncthreads();

        // ---- gates: thread owns (b = tid>>4, jj = 2*(tid&15) .. +1) ----
        {
            int b  = tid >> 4;
            int j2 = (tid & 15) << 1;
            float4 xv = *(float4*)(Xs + b * 4);
            float2 c2 = *(float2*)(Cs + b * JPC + j2);
            float2 zi = *(float2*)(Zs + b * ZS_STRIDE +      j2);
            float2 zf = *(float2*)(Zs + b * ZS_STRIDE + 32 + j2);
            float2 zg = *(float2*)(Zs + b * ZS_STRIDE + 64 + j2);
            float2 zo = *(float2*)(Zs + b * ZS_STRIDE + 96 + j2);
            float ziA[2] = {zi.x, zi.y}, zfA[2] = {zf.x, zf.y};
            float zgA[2] = {zg.x, zg.y}, zoA[2] = {zo.x, zo.y};
            float coA[2] = {c2.x, c2.y};
            float cN[2], hN[2];
            #pragma unroll
            for (int u = 0; u < 2; ++u) {
                int n0 = j2 + u;
                float4 wi = *(float4*)(WihS + (n0)      * 4);
                float4 wf = *(float4*)(WihS + (32 + n0) * 4);
                float4 wg = *(float4*)(WihS + (64 + n0) * 4);
                float4 wo = *(float4*)(WihS + (96 + n0) * 4);
                float ai = ziA[u] + BiasS[n0]      + xv.x*wi.x + xv.y*wi.y + xv.z*wi.z + xv.w*wi.w;
                float af = zfA[u] + BiasS[32 + n0] + xv.x*wf.x + xv.y*wf.y + xv.z*wf.z + xv.w*wf.w;
                float ag = zgA[u] + BiasS[64 + n0] + xv.x*wg.x + xv.y*wg.y + xv.z*wg.z + xv.w*wg.w;
                float ao = zoA[u] + BiasS[96 + n0] + xv.x*wo.x + xv.y*wo.y + xv.z*wo.z + xv.w*wo.w;
                float gi = fast_sigmoid(ai);
                float gf = fast_sigmoid(af);
                float gg = fast_tanh(ag);
                float go = fast_sigmoid(ao);
                float cn = gf * coA[u] + gi * gg;
                cN[u] = cn;
                hN[u] = rtf32(go * fast_tanh(cn));     // pre-round for next mma
            }
            *(float2*)(Cs + b * JPC + j2) = make_float2(cN[0], cN[1]);
            *(float2*)(&g_h[p ^ 1][(size_t)(bbase + b) * HID + j0 + j2]) =
                make_float2(hN[0], hN[1]);
        }
        // release own h writes, acquire peers' (cluster scope)
        asm volatile("barrier.cluster.arrive.aligned;" ::: "memory");
        asm volatile("barrier.cluster.wait.aligned;"   ::: "memory");
    }
    // final h lives in g_h[0] (2048 steps)
}

// ---------------------------------------------------------------------------
// Kernel 3: head
// ---------------------------------------------------------------------------
__global__ void head_kernel(const float* __restrict__ fc_w,
                            const float* __restrict__ fc_b,
                            const float* __restrict__ out_w,
                            const float* __restrict__ out_b,
                            float* __restrict__ out) {
    __shared__ float hsh[HID];
    __shared__ float r0[256];
    __shared__ float r1[256];
    int b = blockIdx.x, tid = threadIdx.x;
    hsh[tid] = g_h[0][b * HID + tid];
    __syncthreads();
    float cf = g_feat[b], ks = g_feat[BATCH + b];
    const float* wr = fc_w + (size_t)tid * (HID + 2);
    float acc = fc_b[tid] + wr[0] * cf + wr[HID + 1] * ks;
    #pragma unroll 8
    for (int k = 0; k < HID; ++k) acc += wr[1 + k] * hsh[k];
    float hid = fmaxf(acc, 0.0f);
    r0[tid] = hid * out_w[tid];
    r1[tid] = hid * out_w[HID + tid];
    __syncthreads();
    for (int o = 128; o > 0; o >>= 1) {
        if (tid < o) { r0[tid] += r0[tid + o]; r1[tid] += r1[tid + o]; }
        __syncthreads();
    }
    if (tid == 0) {
        float l0 = r0[0] + out_b[0];
        float l1 = r1[0] + out_b[1];
        float m  = fmaxf(l0, l1);
        float e0 = __expf(l0 - m), e1 = __expf(l1 - m);
        float inv = __fdividef(1.0f, e0 + e1);
        out[b * 2 + 0] = e0 * inv;
        out[b * 2 + 1] = e1 * inv;
    }
}

// ---------------------------------------------------------------------------
// launch
// ---------------------------------------------------------------------------
extern "C" void kernel_launch(void* const* d_in, const int* in_sizes, int n_in,
                              void* d_out, int out_size) {
    const float* x      = (const float*)d_in[0];
    const float* conv_w = (const float*)d_in[1];
    const float* conv_b = (const float*)d_in[2];
    const float* W_ih   = (const float*)d_in[3];
    const float* W_hh   = (const float*)d_in[4];
    const float* b_ih   = (const float*)d_in[5];
    const float* b_hh   = (const float*)d_in[6];
    const float* fc_w   = (const float*)d_in[7];
    const float* fc_b   = (const float*)d_in[8];
    const float* out_w  = (const float*)d_in[9];
    const float* out_b  = (const float*)d_in[10];
    float* out = (float*)d_out;

    feat_kernel<<<BATCH, 256>>>(x, conv_w, conv_b);
    lstm_kernel<<<NCLUST * CLUSTER, THREADS>>>(x, W_ih, W_hh, b_ih, b_hh);
    head_kernel<<<BATCH, 256>>>(fc_w, fc_b, out_w, out_b, out);
}

// round 5
// speedup vs baseline: 1.1448x; 1.1409x over previous
#include <cuda_runtime.h>
#include <cstdint>

// ---------------------------------------------------------------------------
// Problem constants
// ---------------------------------------------------------------------------
#define BATCH  256
#define SEQ    2048
#define IND    4
#define HID    256

// Partitioning: 8 clusters x 8 CTAs = 64 CTAs (one wave even if same-die).
// Cluster owns MG=32 batch rows; CTA rank r owns h-indices [32r,32r+32)
// -> 128 W_hh rows (4 gates x 32) x 256 cols as tf32 register fragments.
// 8 warps: warp = (kg in {0,1}, nq in {0..3}) -> n-rows [32nq,32nq+32),
// k-half [128kg,128kg+128). k-split halves A-fragment smem traffic.
#define CLUSTER 8
#define NCLUST  8
#define MG      32
#define JPC     32
#define THREADS 256

// A buffer: k-major, interleaved rows, stride 40 words (2-phase LDS.64).
#define AS_KSTR 40
#define AS_BUF  (HID * AS_KSTR)          // 10240 floats per buffer
#define ZS_RSTR 132
#define ZS_BUF  (MG * ZS_RSTR)           // 4224 floats per k-group

// dynamic smem layout (float offsets)
#define OFF_MBAR 0                        // 4 x u64 mbarriers
#define OFF_AS   16
#define OFF_ZS   (OFF_AS + 2 * AS_BUF)    // 20496
#define OFF_WIH  (OFF_ZS + 2 * ZS_BUF)    // 28944
#define OFF_BIAS (OFF_WIH + 512)          // 29456
#define OFF_XS   (OFF_BIAS + 128)         // 29584
#define SMEM_FLOATS (OFF_XS + 2 * MG * 4) // 29840
#define SMEM_BYTES  (SMEM_FLOATS * 4)     // 119360

#define FULL_TX 32768                     // bytes per A buffer fill

// ---------------------------------------------------------------------------
// Global scratch
// ---------------------------------------------------------------------------
__device__ float g_hfin[BATCH * HID];
__device__ float g_feat[2 * BATCH];

// ---------------------------------------------------------------------------
// helpers
// ---------------------------------------------------------------------------
__device__ __forceinline__ uint32_t tf32u(float v) {
    uint32_t r; asm("cvt.rna.tf32.f32 %0, %1;" : "=r"(r) : "f"(v)); return r;
}
__device__ __forceinline__ float rtf32(float v) { return __uint_as_float(tf32u(v)); }
__device__ __forceinline__ float tanh_a(float x) {
    float y; asm("tanh.approx.f32 %0, %1;" : "=f"(y) : "f"(x)); return y;
}
__device__ __forceinline__ float sig_t(float x) { return 0.5f * tanh_a(0.5f * x) + 0.5f; }
__device__ __forceinline__ float fast_sigmoid(float x) {
    float e = __expf(-x); return __fdividef(1.0f, 1.0f + e);
}
__device__ __forceinline__ float dot4(float4 a, float4 b) {
    return a.x * b.x + a.y * b.y + a.z * b.z + a.w * b.w;
}
__device__ __forceinline__ uint32_t smem_u32(const void* p) {
    uint32_t a;
    asm("{ .reg .u64 t; cvta.to.shared.u64 t, %1; cvt.u32.u64 %0, t; }" : "=r"(a) : "l"(p));
    return a;
}
__device__ __forceinline__ uint32_t cta_rank() {
    uint32_t r; asm("mov.u32 %0, %%cluster_ctarank;" : "=r"(r)); return r;
}
__device__ __forceinline__ uint32_t mapa_rank(uint32_t addr, uint32_t rank) {
    uint32_t r; asm("mapa.shared::cluster.u32 %0, %1, %2;" : "=r"(r) : "r"(addr), "r"(rank));
    return r;
}
__device__ __forceinline__ void mbar_init(uint32_t mbar, uint32_t cnt) {
    asm volatile("mbarrier.init.shared.b64 [%0], %1;" :: "r"(mbar), "r"(cnt) : "memory");
}
__device__ __forceinline__ void mbar_expect(uint32_t mbar, uint32_t bytes) {
    asm volatile("mbarrier.arrive.expect_tx.shared.b64 _, [%0], %1;"
                 :: "r"(mbar), "r"(bytes) : "memory");
}
__device__ __forceinline__ void mbar_arrive_remote(uint32_t mbar, uint32_t rank) {
    uint32_t r = mapa_rank(mbar, rank);
    asm volatile("mbarrier.arrive.shared::cluster.b64 _, [%0];" :: "r"(r) : "memory");
}
__device__ __forceinline__ void mbar_wait(uint32_t mbar, uint32_t parity) {
    asm volatile(
        "{\n\t.reg .pred P;\n\t"
        "W_%=:\n\t"
        "mbarrier.try_wait.parity.acquire.cta.shared::cta.b64 P, [%0], %1, 0x989680;\n\t"
        "@P bra D_%=;\n\t"
        "bra W_%=;\n\t"
        "D_%=:\n\t}"
        :: "r"(mbar), "r"(parity) : "memory");
}
__device__ __forceinline__ void st_async2(uint32_t daddr, uint32_t mbar, float a, float b) {
    asm volatile("st.async.shared::cluster.mbarrier::complete_tx::bytes.v2.f32 "
                 "[%0], {%1,%2}, [%3];"
                 :: "r"(daddr), "f"(a), "f"(b), "r"(mbar) : "memory");
}

// ---------------------------------------------------------------------------
// Kernel 1: conv_feat + kernel_sim
// ---------------------------------------------------------------------------
__global__ void feat_kernel(const float* __restrict__ x,
                            const float* __restrict__ conv_w,
                            const float* __restrict__ conv_b) {
    __shared__ float r0[256];
    __shared__ float r1[256];
    int b = blockIdx.x, tid = threadIdx.x;
    float4 cw = *(const float4*)conv_w;
    float cb = conv_b[0];
    const float4* xr = (const float4*)(x + (size_t)b * SEQ * IND);
    float ssig = 0.f, ssq = 0.f;
    for (int s = tid; s < SEQ; s += 256) {
        float4 v = xr[s];
        float d = v.x * cw.x + v.y * cw.y + v.z * cw.z + v.w * cw.w + cb;
        ssig += fast_sigmoid(d);
        ssq  += v.x * v.x + v.y * v.y + v.z * v.z + v.w * v.w;
    }
    r0[tid] = ssig; r1[tid] = ssq;
    __syncthreads();
    for (int o = 128; o > 0; o >>= 1) {
        if (tid < o) { r0[tid] += r0[tid + o]; r1[tid] += r1[tid + o]; }
        __syncthreads();
    }
    if (tid == 0) {
        g_feat[b]         = r0[0] * (1.0f / SEQ);
        g_feat[BATCH + b] = __expf(-r1[0]);
    }
}

// ---------------------------------------------------------------------------
// Kernel 2: LSTM recurrence with DSMEM push exchange.
// ---------------------------------------------------------------------------
__global__ void __cluster_dims__(CLUSTER, 1, 1) __launch_bounds__(THREADS, 1)
lstm_kernel(const float* __restrict__ x,
            const float* __restrict__ W_ih,
            const float* __restrict__ W_hh,
            const float* __restrict__ b_ih,
            const float* __restrict__ b_hh) {
    extern __shared__ float sm[];
    float* As    = sm + OFF_AS;       // As[p] = As + p*AS_BUF, [k][il(row)] stride 40
    float* Zs    = sm + OFF_ZS;       // Zs[kg] = Zs + kg*ZS_BUF, [row][n] stride 132
    float* WihS  = sm + OFF_WIH;      // [128][4]
    float* BiasS = sm + OFF_BIAS;     // [128]
    float* Xs    = sm + OFF_XS;       // Xs[p] = +p*128, [row][4]

    const uint32_t sbase   = smem_u32(sm);
    const uint32_t mbfull0 = sbase + 0, mbfull1 = sbase + 8;
    const uint32_t mbdone0 = sbase + 16, mbdone1 = sbase + 24;

    const int tid   = threadIdx.x;
    const int cid   = blockIdx.x / CLUSTER;
    const uint32_t rank = cta_rank();
    const int bbase = cid * MG;
    const int j0    = (int)rank * JPC;
    const int warp  = tid >> 5, lane = tid & 31;
    const int kg    = warp >> 2, nq = warp & 3;
    const int g     = lane >> 2, tig = lane & 3;

    // ---- one-time: W_hh register fragments (tf32) ----
    uint32_t Breg[4][16][2];
    #pragma unroll
    for (int s = 0; s < 4; ++s) {
        const int nl   = nq * 32 + s * 8 + g;
        const int gate = nl >> 5, jj = nl & 31;
        const float* wrow = W_hh + (size_t)(gate * HID + j0 + jj) * HID + kg * 128;
        #pragma unroll
        for (int kt = 0; kt < 16; ++kt) {
            Breg[s][kt][0] = tf32u(wrow[kt * 8 + tig]);
            Breg[s][kt][1] = tf32u(wrow[kt * 8 + tig + 4]);
        }
    }
    if (tid < 128) {
        int gate = tid >> 5, jj = tid & 31;
        int grow = gate * HID + j0 + jj;
        BiasS[tid] = b_ih[grow] + b_hh[grow];
        WihS[tid * 4 + 0] = W_ih[grow * IND + 0];
        WihS[tid * 4 + 1] = W_ih[grow * IND + 1];
        WihS[tid * 4 + 2] = W_ih[grow * IND + 2];
        WihS[tid * 4 + 3] = W_ih[grow * IND + 3];
    }
    // zero As[0] (h_0 = 0)
    for (int i = tid; i < AS_BUF; i += THREADS) As[i] = 0.0f;
    // stage x_0
    if (tid < MG)
        *(float4*)(Xs + tid * 4) = *(const float4*)(x + (size_t)(bbase + tid) * SEQ * IND);
    // mbarriers
    if (tid == 0) {
        mbar_init(mbfull0, 1); mbar_init(mbfull1, 1);
        mbar_init(mbdone0, 8); mbar_init(mbdone1, 8);
        asm volatile("fence.mbarrier_init.release.cluster;" ::: "memory");
        mbar_expect(mbfull0, FULL_TX);     // phase 0 arm (filled at t=1)
        mbar_expect(mbfull1, FULL_TX);     // phase 0 arm (filled at t=0)
    }
    __syncthreads();
    asm volatile("barrier.cluster.arrive.aligned;" ::: "memory");
    asm volatile("barrier.cluster.wait.aligned;"   ::: "memory");

    const int jl = tid & 31;      // gate-phase ownership: column j0+jl,
    const int rr = tid >> 5;      // rows {rr, rr+8, rr+16, rr+24}
    float cst[4] = {0.f, 0.f, 0.f, 0.f};
    uint32_t pf[2] = {0, 0}, pd[2] = {0, 0};

    for (int t = 0; t < SEQ; ++t) {
        const int p = t & 1;
        const uint32_t mbfull_p  = p ? mbfull1 : mbfull0;
        const uint32_t mbfull_n  = p ? mbfull0 : mbfull1;
        const uint32_t mbdone_p  = p ? mbdone1 : mbdone0;
        const uint32_t mbdone_n  = p ? mbdone0 : mbdone1;

        // prefetch x_{t+1}
        float4 xpre;
        const bool do_x = (tid < MG) && (t + 1 < SEQ);
        if (do_x)
            xpre = *(const float4*)(x + ((size_t)(bbase + tid) * SEQ + (t + 1)) * IND);

        // wait for A buffer p (step 0: locally zeroed)
        if (t > 0) {
            mbar_wait(mbfull_p, pf[p]);
            pf[p] ^= 1;
            if (tid == 0) mbar_expect(mbfull_p, FULL_TX);   // arm next phase
        }

        // ---- z_partial(kg) = h @ W^T for this warp's 32 n-rows ----
        const uint32_t* Au = (const uint32_t*)(As + p * AS_BUF);
        float acc[2][4][4];
        #pragma unroll
        for (int mt = 0; mt < 2; ++mt)
            #pragma unroll
            for (int s = 0; s < 4; ++s)
                #pragma unroll
                for (int q = 0; q < 4; ++q) acc[mt][s][q] = 0.0f;

        #pragma unroll
        for (int kt = 0; kt < 16; ++kt) {
            const int kb = kg * 128 + kt * 8 + tig;
            uint2 A0  = *(const uint2*)(Au + (size_t)kb * AS_KSTR + 2 * g);
            uint2 A0b = *(const uint2*)(Au + (size_t)(kb + 4) * AS_KSTR + 2 * g);
            uint2 A1  = *(const uint2*)(Au + (size_t)kb * AS_KSTR + 16 + 2 * g);
            uint2 A1b = *(const uint2*)(Au + (size_t)(kb + 4) * AS_KSTR + 16 + 2 * g);
            #pragma unroll
            for (int s = 0; s < 4; ++s) {
                asm("mma.sync.aligned.m16n8k8.row.col.f32.tf32.tf32.f32 "
                    "{%0,%1,%2,%3},{%4,%5,%6,%7},{%8,%9},{%0,%1,%2,%3};"
                    : "+f"(acc[0][s][0]), "+f"(acc[0][s][1]), "+f"(acc[0][s][2]), "+f"(acc[0][s][3])
                    : "r"(A0.x), "r"(A0.y), "r"(A0b.x), "r"(A0b.y),
                      "r"(Breg[s][kt][0]), "r"(Breg[s][kt][1]));
                asm("mma.sync.aligned.m16n8k8.row.col.f32.tf32.tf32.f32 "
                    "{%0,%1,%2,%3},{%4,%5,%6,%7},{%8,%9},{%0,%1,%2,%3};"
                    : "+f"(acc[1][s][0]), "+f"(acc[1][s][1]), "+f"(acc[1][s][2]), "+f"(acc[1][s][3])
                    : "r"(A1.x), "r"(A1.y), "r"(A1b.x), "r"(A1b.y),
                      "r"(Breg[s][kt][0]), "r"(Breg[s][kt][1]));
            }
        }
        {
            float* Zp = Zs + kg * ZS_BUF;
            #pragma unroll
            for (int mt = 0; mt < 2; ++mt)
                #pragma unroll
                for (int s = 0; s < 4; ++s) {
                    const int n0 = nq * 32 + s * 8;
                    const int r0 = mt * 16 + g;
                    *(float2*)(Zp + (size_t)r0 * ZS_RSTR + n0 + 2 * tig) =
                        make_float2(acc[mt][s][0], acc[mt][s][1]);
                    *(float2*)(Zp + (size_t)(r0 + 8) * ZS_RSTR + n0 + 2 * tig) =
                        make_float2(acc[mt][s][2], acc[mt][s][3]);
                }
        }
        __syncthreads();

        // signal "A buffer p consumed" to all cluster CTAs
        if (tid == 0) {
            #pragma unroll
            for (uint32_t rk = 0; rk < CLUSTER; ++rk) mbar_arrive_remote(mbdone_p, rk);
        }
        // stash prefetched x
        if (do_x) *(float4*)(Xs + (p ^ 1) * (MG * 4) + tid * 4) = xpre;

        // ---- gates: thread owns column jl for rows {rr, rr+8, rr+16, rr+24} ----
        float hv[4];
        {
            const float4 wiv = *(const float4*)(WihS + (jl)      * 4);
            const float4 wfv = *(const float4*)(WihS + (32 + jl) * 4);
            const float4 wgv = *(const float4*)(WihS + (64 + jl) * 4);
            const float4 wov = *(const float4*)(WihS + (96 + jl) * 4);
            const float bi = BiasS[jl], bf = BiasS[32 + jl];
            const float bg = BiasS[64 + jl], bo = BiasS[96 + jl];
            #pragma unroll
            for (int q = 0; q < 4; ++q) {
                const int r = rr + 8 * q;
                const float4 xv = *(const float4*)(Xs + p * (MG * 4) + r * 4);
                const float* z0 = Zs + (size_t)r * ZS_RSTR;
                const float* z1 = z0 + ZS_BUF;
                const float ai = z0[jl]      + z1[jl]      + bi + dot4(wiv, xv);
                const float af = z0[32 + jl] + z1[32 + jl] + bf + dot4(wfv, xv);
                const float ag = z0[64 + jl] + z1[64 + jl] + bg + dot4(wgv, xv);
                const float ao = z0[96 + jl] + z1[96 + jl] + bo + dot4(wov, xv);
                const float gi = sig_t(ai), gf = sig_t(af), go = sig_t(ao);
                const float gg = tanh_a(ag);
                const float cn = gf * cst[q] + gi * gg;
                cst[q] = cn;
                hv[q] = rtf32(go * tanh_a(cn));
            }
        }

        // wait until all CTAs consumed A buffer p^1 (its previous contents)
        if (t > 0) {
            mbar_wait(mbdone_n, pd[p ^ 1]);
            pd[p ^ 1] ^= 1;
        }

        // push h into every CTA's A buffer p^1 (fragment-interleaved layout)
        {
            const uint32_t w0 = (uint32_t)(OFF_AS + (p ^ 1) * AS_BUF + (j0 + jl) * AS_KSTR);
            const uint32_t d0 = sbase + (w0 + 2 * rr) * 4;        // rows rr, rr+8   (mt0)
            const uint32_t d1 = sbase + (w0 + 16 + 2 * rr) * 4;   // rows rr+16,+24  (mt1)
            const uint32_t mb = p ? mbfull0 : mbfull1;            // peer full[p^1]
            #pragma unroll
            for (uint32_t rk = 0; rk < CLUSTER; ++rk) {
                const uint32_t rm = mapa_rank(mb, rk);
                st_async2(mapa_rank(d0, rk), rm, hv[0], hv[1]);
                st_async2(mapa_rank(d1, rk), rm, hv[2], hv[3]);
            }
        }

        if (t == SEQ - 1) {
            #pragma unroll
            for (int q = 0; q < 4; ++q)
                g_hfin[(size_t)(bbase + rr + 8 * q) * HID + j0 + jl] = hv[q];
        }
    }

    // drain final incoming writes (t=2047 targeted full[0]) before exit
    mbar_wait(mbfull0, pf[0]);
    asm volatile("barrier.cluster.arrive.aligned;" ::: "memory");
    asm volatile("barrier.cluster.wait.aligned;"   ::: "memory");
}

// ---------------------------------------------------------------------------
// Kernel 3: head
// ---------------------------------------------------------------------------
__global__ void head_kernel(const float* __restrict__ fc_w,
                            const float* __restrict__ fc_b,
                            const float* __restrict__ out_w,
                            const float* __restrict__ out_b,
                            float* __restrict__ out) {
    __shared__ float hsh[HID];
    __shared__ float r0[256];
    __shared__ float r1[256];
    int b = blockIdx.x, tid = threadIdx.x;
    hsh[tid] = g_hfin[b * HID + tid];
    __syncthreads();
    float cf = g_feat[b], ks = g_feat[BATCH + b];
    const float* wr = fc_w + (size_t)tid * (HID + 2);
    float acc = fc_b[tid] + wr[0] * cf + wr[HID + 1] * ks;
    #pragma unroll 8
    for (int k = 0; k < HID; ++k) acc += wr[1 + k] * hsh[k];
    float hid = fmaxf(acc, 0.0f);
    r0[tid] = hid * out_w[tid];
    r1[tid] = hid * out_w[HID + tid];
    __syncthreads();
    for (int o = 128; o > 0; o >>= 1) {
        if (tid < o) { r0[tid] += r0[tid + o]; r1[tid] += r1[tid + o]; }
        __syncthreads();
    }
    if (tid == 0) {
        float l0 = r0[0] + out_b[0];
        float l1 = r1[0] + out_b[1];
        float m  = fmaxf(l0, l1);
        float e0 = __expf(l0 - m), e1 = __expf(l1 - m);
        float inv = __fdividef(1.0f, e0 + e1);
        out[b * 2 + 0] = e0 * inv;
        out[b * 2 + 1] = e1 * inv;
    }
}

// ---------------------------------------------------------------------------
// launch
// ---------------------------------------------------------------------------
extern "C" void kernel_launch(void* const* d_in, const int* in_sizes, int n_in,
                              void* d_out, int out_size) {
    const float* x      = (const float*)d_in[0];
    const float* conv_w = (const float*)d_in[1];
    const float* conv_b = (const float*)d_in[2];
    const float* W_ih   = (const float*)d_in[3];
    const float* W_hh   = (const float*)d_in[4];
    const float* b_ih   = (const float*)d_in[5];
    const float* b_hh   = (const float*)d_in[6];
    const float* fc_w   = (const float*)d_in[7];
    const float* fc_b   = (const float*)d_in[8];
    const float* out_w  = (const float*)d_in[9];
    const float* out_b  = (const float*)d_in[10];
    float* out = (float*)d_out;

    cudaFuncSetAttribute(lstm_kernel, cudaFuncAttributeMaxDynamicSharedMemorySize,
                         SMEM_BYTES);

    feat_kernel<<<BATCH, 256>>>(x, conv_w, conv_b);
    lstm_kernel<<<NCLUST * CLUSTER, THREADS, SMEM_BYTES>>>(x, W_ih, W_hh, b_ih, b_hh);
    head_kernel<<<BATCH, 256>>>(fc_w, fc_b, out_w, out_b, out);
}

// round 6
// speedup vs baseline: 2.1935x; 1.9161x over previous
#include <cuda_runtime.h>
#include <cstdint>

// ---------------------------------------------------------------------------
// Problem constants
// ---------------------------------------------------------------------------
#define BATCH  256
#define SEQ    2048
#define IND    4
#define HID    256

// 8 clusters x 8 CTAs = 64 CTAs (single wave on one die).
// Cluster owns MG=32 batch rows; CTA rank r owns h-indices [32r,32r+32)
// -> 128 W_hh rows (4 gates x 32) x 256 cols as tf32 register fragments.
// 8 warps: warp = (kg in {0,1}, nq in {0..3}).
#define CLUSTER 8
#define NCLUST  8
#define MG      32
#define JPC     32
#define THREADS 256

// A buffer: k-major, interleaved batch rows, stride 40 words.
#define AS_KSTR 40
#define AS_BUF  (HID * AS_KSTR)          // 10240 floats per buffer
#define ZS_RSTR 132
#define ZS_BUF  (MG * ZS_RSTR)           // 4224 floats per k-group
#define SLICE_W (JPC * AS_KSTR)          // 1280 words per CTA slice
#define SLICE_B (SLICE_W * 4)            // 5120 bytes

// dynamic smem layout (float offsets)
#define OFF_AS    16
#define OFF_ZS    (OFF_AS + 2 * AS_BUF)     // 20496
#define OFF_WIH   (OFF_ZS + 2 * ZS_BUF)     // 28944
#define OFF_BIAS  (OFF_WIH + 512)           // 29456
#define OFF_XS    (OFF_BIAS + 128)          // 29584
#define OFF_STAGE (OFF_XS + 2 * MG * 4)     // 29840
#define SMEM_FLOATS (OFF_STAGE + 2 * SLICE_W) // 32400
#define SMEM_BYTES  (SMEM_FLOATS * 4)        // 129600

#define FULL_TX (7 * SLICE_B)             // 35840 bytes from 7 peers

// ---------------------------------------------------------------------------
// Global scratch
// ---------------------------------------------------------------------------
__device__ float g_hfin[BATCH * HID];
__device__ float g_feat[2 * BATCH];

// ---------------------------------------------------------------------------
// helpers
// ---------------------------------------------------------------------------
__device__ __forceinline__ uint32_t tf32u(float v) {
    uint32_t r; asm("cvt.rna.tf32.f32 %0, %1;" : "=r"(r) : "f"(v)); return r;
}
__device__ __forceinline__ float rtf32(float v) { return __uint_as_float(tf32u(v)); }
__device__ __forceinline__ float tanh_a(float x) {
    float y; asm("tanh.approx.f32 %0, %1;" : "=f"(y) : "f"(x)); return y;
}
__device__ __forceinline__ float sig_t(float x) { return 0.5f * tanh_a(0.5f * x) + 0.5f; }
__device__ __forceinline__ float fast_sigmoid(float x) {
    float e = __expf(-x); return __fdividef(1.0f, 1.0f + e);
}
__device__ __forceinline__ float dot4(float4 a, float4 b) {
    return a.x * b.x + a.y * b.y + a.z * b.z + a.w * b.w;
}
__device__ __forceinline__ uint32_t smem_u32(const void* p) {
    uint32_t a;
    asm("{ .reg .u64 t; cvta.to.shared.u64 t, %1; cvt.u32.u64 %0, t; }" : "=r"(a) : "l"(p));
    return a;
}
__device__ __forceinline__ uint32_t cta_rank() {
    uint32_t r; asm("mov.u32 %0, %%cluster_ctarank;" : "=r"(r)); return r;
}
__device__ __forceinline__ uint32_t mapa_rank(uint32_t addr, uint32_t rank) {
    uint32_t r; asm("mapa.shared::cluster.u32 %0, %1, %2;" : "=r"(r) : "r"(addr), "r"(rank));
    return r;
}
__device__ __forceinline__ void mbar_init(uint32_t mbar, uint32_t cnt) {
    asm volatile("mbarrier.init.shared.b64 [%0], %1;" :: "r"(mbar), "r"(cnt) : "memory");
}
__device__ __forceinline__ void mbar_expect(uint32_t mbar, uint32_t bytes) {
    asm volatile("mbarrier.arrive.expect_tx.shared.b64 _, [%0], %1;"
                 :: "r"(mbar), "r"(bytes) : "memory");
}
__device__ __forceinline__ void mbar_arrive_remote(uint32_t mbar, uint32_t rank) {
    uint32_t r = mapa_rank(mbar, rank);
    asm volatile("mbarrier.arrive.shared::cluster.b64 _, [%0];" :: "r"(r) : "memory");
}
__device__ __forceinline__ void mbar_wait(uint32_t mbar, uint32_t parity) {
    asm volatile(
        "{\n\t.reg .pred P;\n\t"
        "W_%=:\n\t"
        "mbarrier.try_wait.parity.acquire.cta.shared::cta.b64 P, [%0], %1, 0x989680;\n\t"
        "@P bra D_%=;\n\t"
        "bra W_%=;\n\t"
        "D_%=:\n\t}"
        :: "r"(mbar), "r"(parity) : "memory");
}
__device__ __forceinline__ void bulk_s2s(uint32_t dst, uint32_t src, uint32_t bytes,
                                         uint32_t mbar) {
    asm volatile("cp.async.bulk.shared::cluster.shared::cta."
                 "mbarrier::complete_tx::bytes [%0], [%1], %2, [%3];"
                 :: "r"(dst), "r"(src), "r"(bytes), "r"(mbar) : "memory");
}

// ---------------------------------------------------------------------------
// Kernel 1: conv_feat + kernel_sim
// ---------------------------------------------------------------------------
__global__ void feat_kernel(const float* __restrict__ x,
                            const float* __restrict__ conv_w,
                            const float* __restrict__ conv_b) {
    __shared__ float r0[256];
    __shared__ float r1[256];
    int b = blockIdx.x, tid = threadIdx.x;
    float4 cw = *(const float4*)conv_w;
    float cb = conv_b[0];
    const float4* xr = (const float4*)(x + (size_t)b * SEQ * IND);
    float ssig = 0.f, ssq = 0.f;
    for (int s = tid; s < SEQ; s += 256) {
        float4 v = xr[s];
        float d = v.x * cw.x + v.y * cw.y + v.z * cw.z + v.w * cw.w + cb;
        ssig += fast_sigmoid(d);
        ssq  += v.x * v.x + v.y * v.y + v.z * v.z + v.w * v.w;
    }
    r0[tid] = ssig; r1[tid] = ssq;
    __syncthreads();
    for (int o = 128; o > 0; o >>= 1) {
        if (tid < o) { r0[tid] += r0[tid + o]; r1[tid] += r1[tid + o]; }
        __syncthreads();
    }
    if (tid == 0) {
        g_feat[b]         = r0[0] * (1.0f / SEQ);
        g_feat[BATCH + b] = __expf(-r1[0]);
    }
}

// ---------------------------------------------------------------------------
// Kernel 2: LSTM recurrence; exchange via cp.async.bulk DSMEM (7 tx/step/dst)
// ---------------------------------------------------------------------------
__global__ void __cluster_dims__(CLUSTER, 1, 1) __launch_bounds__(THREADS, 1)
lstm_kernel(const float* __restrict__ x,
            const float* __restrict__ W_ih,
            const float* __restrict__ W_hh,
            const float* __restrict__ b_ih,
            const float* __restrict__ b_hh) {
    extern __shared__ float sm[];
    float* As    = sm + OFF_AS;
    float* Zs    = sm + OFF_ZS;
    float* WihS  = sm + OFF_WIH;
    float* BiasS = sm + OFF_BIAS;
    float* Xs    = sm + OFF_XS;
    float* Stg   = sm + OFF_STAGE;

    const uint32_t sbase   = smem_u32(sm);
    const uint32_t mbfull0 = sbase + 0,  mbfull1 = sbase + 8;
    const uint32_t mbdone0 = sbase + 16, mbdone1 = sbase + 24;

    const int tid   = threadIdx.x;
    const int cid   = blockIdx.x / CLUSTER;
    const uint32_t rank = cta_rank();
    const int bbase = cid * MG;
    const int j0    = (int)rank * JPC;
    const int warp  = tid >> 5, lane = tid & 31;
    const int kg    = warp >> 2, nq = warp & 3;
    const int g     = lane >> 2, tig = lane & 3;

    // ---- one-time: W_hh register fragments (tf32) ----
    uint32_t Breg[4][16][2];
    #pragma unroll
    for (int s = 0; s < 4; ++s) {
        const int nl   = nq * 32 + s * 8 + g;
        const int gate = nl >> 5, jj = nl & 31;
        const float* wrow = W_hh + (size_t)(gate * HID + j0 + jj) * HID + kg * 128;
        #pragma unroll
        for (int kt = 0; kt < 16; ++kt) {
            Breg[s][kt][0] = tf32u(wrow[kt * 8 + tig]);
            Breg[s][kt][1] = tf32u(wrow[kt * 8 + tig + 4]);
        }
    }
    if (tid < 128) {
        int gate = tid >> 5, jj = tid & 31;
        int grow = gate * HID + j0 + jj;
        BiasS[tid] = b_ih[grow] + b_hh[grow];
        WihS[tid * 4 + 0] = W_ih[grow * IND + 0];
        WihS[tid * 4 + 1] = W_ih[grow * IND + 1];
        WihS[tid * 4 + 2] = W_ih[grow * IND + 2];
        WihS[tid * 4 + 3] = W_ih[grow * IND + 3];
    }
    for (int i = tid; i < AS_BUF; i += THREADS) As[i] = 0.0f;   // h_0 = 0
    if (tid < MG)
        *(float4*)(Xs + tid * 4) = *(const float4*)(x + (size_t)(bbase + tid) * SEQ * IND);
    if (tid == 0) {
        mbar_init(mbfull0, 1); mbar_init(mbfull1, 1);
        mbar_init(mbdone0, 8); mbar_init(mbdone1, 8);
        asm volatile("fence.mbarrier_init.release.cluster;" ::: "memory");
        mbar_expect(mbfull0, FULL_TX);
        mbar_expect(mbfull1, FULL_TX);
    }
    __syncthreads();
    asm volatile("barrier.cluster.arrive.aligned;" ::: "memory");
    asm volatile("barrier.cluster.wait.aligned;"   ::: "memory");

    // gate-phase ownership: col jl = tid&31, q-hat = tid>>5 ->
    // batch rows {base+2qq, base+2qq+8, base+2qq+1, base+2qq+9} (word order)
    const int jl  = tid & 31;
    const int qh  = tid >> 5;
    const int qq  = qh & 3;
    const int rbq = (qh & 4) ? 16 : 0;
    const int rows[4] = { rbq + 2*qq, rbq + 2*qq + 8, rbq + 2*qq + 1, rbq + 2*qq + 9 };
    float cst[4] = {0.f, 0.f, 0.f, 0.f};
    uint32_t pf[2] = {0, 0}, pd[2] = {0, 0};

    for (int t = 0; t < SEQ; ++t) {
        const int p = t & 1;
        const uint32_t mbfull_p = p ? mbfull1 : mbfull0;
        const uint32_t mbfull_n = p ? mbfull0 : mbfull1;   // target of this step's push
        const uint32_t mbdone_p = p ? mbdone1 : mbdone0;
        const uint32_t mbdone_n = p ? mbdone0 : mbdone1;

        // prefetch x_{t+1}
        float4 xpre;
        const bool do_x = (tid < MG) && (t + 1 < SEQ);
        if (do_x)
            xpre = *(const float4*)(x + ((size_t)(bbase + tid) * SEQ + (t + 1)) * IND);

        if (t > 0) {
            mbar_wait(mbfull_p, pf[p]);
            pf[p] ^= 1;
            if (tid == 0) mbar_expect(mbfull_p, FULL_TX);
        }

        // ---- z_partial(kg) = h @ W^T for this warp's 32 n-rows ----
        const uint32_t* Au = (const uint32_t*)(As + p * AS_BUF);
        float acc[2][4][4];
        #pragma unroll
        for (int mt = 0; mt < 2; ++mt)
            #pragma unroll
            for (int s = 0; s < 4; ++s)
                #pragma unroll
                for (int q = 0; q < 4; ++q) acc[mt][s][q] = 0.0f;

        #pragma unroll
        for (int kt = 0; kt < 16; ++kt) {
            const int kb = kg * 128 + kt * 8 + tig;
            uint2 A0  = *(const uint2*)(Au + (size_t)kb * AS_KSTR + 2 * g);
            uint2 A0b = *(const uint2*)(Au + (size_t)(kb + 4) * AS_KSTR + 2 * g);
            uint2 A1  = *(const uint2*)(Au + (size_t)kb * AS_KSTR + 16 + 2 * g);
            uint2 A1b = *(const uint2*)(Au + (size_t)(kb + 4) * AS_KSTR + 16 + 2 * g);
            #pragma unroll
            for (int s = 0; s < 4; ++s) {
                asm("mma.sync.aligned.m16n8k8.row.col.f32.tf32.tf32.f32 "
                    "{%0,%1,%2,%3},{%4,%5,%6,%7},{%8,%9},{%0,%1,%2,%3};"
                    : "+f"(acc[0][s][0]), "+f"(acc[0][s][1]), "+f"(acc[0][s][2]), "+f"(acc[0][s][3])
                    : "r"(A0.x), "r"(A0.y), "r"(A0b.x), "r"(A0b.y),
                      "r"(Breg[s][kt][0]), "r"(Breg[s][kt][1]));
                asm("mma.sync.aligned.m16n8k8.row.col.f32.tf32.tf32.f32 "
                    "{%0,%1,%2,%3},{%4,%5,%6,%7},{%8,%9},{%0,%1,%2,%3};"
                    : "+f"(acc[1][s][0]), "+f"(acc[1][s][1]), "+f"(acc[1][s][2]), "+f"(acc[1][s][3])
                    : "r"(A1.x), "r"(A1.y), "r"(A1b.x), "r"(A1b.y),
                      "r"(Breg[s][kt][0]), "r"(Breg[s][kt][1]));
            }
        }
        {
            float* Zp = Zs + kg * ZS_BUF;
            #pragma unroll
            for (int mt = 0; mt < 2; ++mt)
                #pragma unroll
                for (int s = 0; s < 4; ++s) {
                    const int n0 = nq * 32 + s * 8;
                    const int r0 = mt * 16 + g;
                    *(float2*)(Zp + (size_t)r0 * ZS_RSTR + n0 + 2 * tig) =
                        make_float2(acc[mt][s][0], acc[mt][s][1]);
                    *(float2*)(Zp + (size_t)(r0 + 8) * ZS_RSTR + n0 + 2 * tig) =
                        make_float2(acc[mt][s][2], acc[mt][s][3]);
                }
        }
        // recycle staging buffer (t&1): its bulk group from step t-2 must be read-done
        if (tid == 0) asm volatile("cp.async.bulk.wait_group.read 1;" ::: "memory");
        __syncthreads();

        // signal "A buffer p consumed" to all cluster CTAs
        if (tid == 0) {
            #pragma unroll
            for (uint32_t rk = 0; rk < CLUSTER; ++rk) mbar_arrive_remote(mbdone_p, rk);
        }
        if (do_x) *(float4*)(Xs + (p ^ 1) * (MG * 4) + tid * 4) = xpre;

        // ---- gates ----
        float hv[4];
        {
            const float4 wiv = *(const float4*)(WihS + (jl)      * 4);
            const float4 wfv = *(const float4*)(WihS + (32 + jl) * 4);
            const float4 wgv = *(const float4*)(WihS + (64 + jl) * 4);
            const float4 wov = *(const float4*)(WihS + (96 + jl) * 4);
            const float bi = BiasS[jl], bf = BiasS[32 + jl];
            const float bg = BiasS[64 + jl], bo = BiasS[96 + jl];
            #pragma unroll
            for (int q = 0; q < 4; ++q) {
                const int r = rows[q];
                const float4 xv = *(const float4*)(Xs + p * (MG * 4) + r * 4);
                const float* z0 = Zs + (size_t)r * ZS_RSTR;
                const float* z1 = z0 + ZS_BUF;
                const float ai = z0[jl]      + z1[jl]      + bi + dot4(wiv, xv);
                const float af = z0[32 + jl] + z1[32 + jl] + bf + dot4(wfv, xv);
                const float ag = z0[64 + jl] + z1[64 + jl] + bg + dot4(wgv, xv);
                const float ao = z0[96 + jl] + z1[96 + jl] + bo + dot4(wov, xv);
                const float gi = sig_t(ai), gf = sig_t(af), go = sig_t(ao);
                const float gg = tanh_a(ag);
                const float cn = gf * cst[q] + gi * gg;
                cst[q] = cn;
                hv[q] = rtf32(go * tanh_a(cn));
            }
        }
        // write own h: staging (for bulk) + directly into own As[p^1]
        {
            float4 hq = make_float4(hv[0], hv[1], hv[2], hv[3]);
            *(float4*)(Stg + (t & 1) * SLICE_W + jl * AS_KSTR + 4 * qh) = hq;
            *(float4*)(As + (p ^ 1) * AS_BUF + (size_t)(j0 + jl) * AS_KSTR + 4 * qh) = hq;
        }
        __syncthreads();   // staging + self-slice complete

        // elected: wait peers consumed As[p^1], then bulk-push slice to 7 peers
        if (tid == 0) {
            if (t > 0) { mbar_wait(mbdone_n, pd[p ^ 1]); pd[p ^ 1] ^= 1; }
            asm volatile("fence.proxy.async.shared::cta;" ::: "memory");
            const uint32_t src  = sbase + (OFF_STAGE + (t & 1) * SLICE_W) * 4;
            const uint32_t dstl = sbase + (OFF_AS + (p ^ 1) * AS_BUF + j0 * AS_KSTR) * 4;
            #pragma unroll
            for (uint32_t rk = 0; rk < CLUSTER; ++rk) {
                if (rk == rank) continue;
                bulk_s2s(mapa_rank(dstl, rk), src, SLICE_B, mapa_rank(mbfull_n, rk));
            }
            asm volatile("cp.async.bulk.commit_group;" ::: "memory");
        }

        if (t == SEQ - 1) {
            #pragma unroll
            for (int q = 0; q < 4; ++q)
                g_hfin[(size_t)(bbase + rows[q]) * HID + j0 + jl] = hv[q];
        }
    }

    // drain final incoming bulks (t=2047 targeted full[0]) before exit
    mbar_wait(mbfull0, pf[0]);
    asm volatile("barrier.cluster.arrive.aligned;" ::: "memory");
    asm volatile("barrier.cluster.wait.aligned;"   ::: "memory");
}

// ---------------------------------------------------------------------------
// Kernel 3: head
// ---------------------------------------------------------------------------
__global__ void head_kernel(const float* __restrict__ fc_w,
                            const float* __restrict__ fc_b,
                            const float* __restrict__ out_w,
                            const float* __restrict__ out_b,
                            float* __restrict__ out) {
    __shared__ float hsh[HID];
    __shared__ float r0[256];
    __shared__ float r1[256];
    int b = blockIdx.x, tid = threadIdx.x;
    hsh[tid] = g_hfin[b * HID + tid];
    __syncthreads();
    float cf = g_feat[b], ks = g_feat[BATCH + b];
    const float* wr = fc_w + (size_t)tid * (HID + 2);
    float acc = fc_b[tid] + wr[0] * cf + wr[HID + 1] * ks;
    #pragma unroll 8
    for (int k = 0; k < HID; ++k) acc += wr[1 + k] * hsh[k];
    float hid = fmaxf(acc, 0.0f);
    r0[tid] = hid * out_w[tid];
    r1[tid] = hid * out_w[HID + tid];
    __syncthreads();
    for (int o = 128; o > 0; o >>= 1) {
        if (tid < o) { r0[tid] += r0[tid + o]; r1[tid] += r1[tid + o]; }
        __syncthreads();
    }
    if (tid == 0) {
        float l0 = r0[0] + out_b[0];
        float l1 = r1[0] + out_b[1];
        float m  = fmaxf(l0, l1);
        float e0 = __expf(l0 - m), e1 = __expf(l1 - m);
        float inv = __fdividef(1.0f, e0 + e1);
        out[b * 2 + 0] = e0 * inv;
        out[b * 2 + 1] = e1 * inv;
    }
}

// ---------------------------------------------------------------------------
// launch (lstm first so the fixed ncu sampling slot captures it)
// ---------------------------------------------------------------------------
extern "C" void kernel_launch(void* const* d_in, const int* in_sizes, int n_in,
                              void* d_out, int out_size) {
    const float* x      = (const float*)d_in[0];
    const float* conv_w = (const float*)d_in[1];
    const float* conv_b = (const float*)d_in[2];
    const float* W_ih   = (const float*)d_in[3];
    const float* W_hh   = (const float*)d_in[4];
    const float* b_ih   = (const float*)d_in[5];
    const float* b_hh   = (const float*)d_in[6];
    const float* fc_w   = (const float*)d_in[7];
    const float* fc_b   = (const float*)d_in[8];
    const float* out_w  = (const float*)d_in[9];
    const float* out_b  = (const float*)d_in[10];
    float* out = (float*)d_out;

    cudaFuncSetAttribute(lstm_kernel, cudaFuncAttributeMaxDynamicSharedMemorySize,
                         SMEM_BYTES);

    lstm_kernel<<<NCLUST * CLUSTER, THREADS, SMEM_BYTES>>>(x, W_ih, W_hh, b_ih, b_hh);
    feat_kernel<<<BATCH, 256>>>(x, conv_w, conv_b);
    head_kernel<<<BATCH, 256>>>(fc_w, fc_b, out_w, out_b, out);
}